// round 14
// baseline (speedup 1.0000x reference)
#include <cuda_runtime.h>
#include <cuda_bf16.h>
#include <cstdint>
#include <math.h>

// ---------------- problem constants ----------------
#define BATCH 2
#define TT    2048
#define TOK   4096          // BATCH*TT
#define DD    1024
#define DI    2048
#define XZN   4096          // 2*DI
#define NSTATE 16
#define DTR   64
#define PROJN 96            // DTR + 2*NSTATE
#define DFF   2048
#define NE    8
#define CAP   4096          // max tokens per expert
#define NCHUNK 128
#define CL    (TT / NCHUNK) // 16

// ---------------- unified scratch (single symbol; no allocs) ----------------
constexpr size_t O_XZ   = 0;
constexpr size_t O_XC   = O_XZ   + (size_t)TOK*XZN*4;
constexpr size_t O_PROJ = O_XC   + (size_t)TOK*DI*4;
constexpr size_t O_DT   = O_PROJ + (size_t)TOK*PROJN*4;
constexpr size_t O_HM   = O_DT   + (size_t)TOK*DI*4;
constexpr size_t O_YE   = O_HM   + (size_t)TOK*DD*4;
constexpr size_t O_HNH  = O_YE   + (size_t)NE*CAP*DD*4;
constexpr size_t O_HNL  = O_HNH  + (size_t)TOK*DD*2;
constexpr size_t O_INWH = O_HNL  + (size_t)TOK*DD*2;
constexpr size_t O_INWL = O_INWH + (size_t)XZN*DD*2;
constexpr size_t O_XCH  = O_INWL + (size_t)XZN*DD*2;
constexpr size_t O_XCL  = O_XCH  + (size_t)TOK*DI*2;
constexpr size_t O_XPWH = O_XCL  + (size_t)TOK*DI*2;
constexpr size_t O_XPWL = O_XPWH + (size_t)128*DI*2;
constexpr size_t O_DTAH = O_XPWL + (size_t)128*DI*2;
constexpr size_t O_DTAL = O_DTAH + (size_t)TOK*DTR*2;
constexpr size_t O_DTWH = O_DTAL + (size_t)TOK*DTR*2;
constexpr size_t O_DTWL = O_DTWH + (size_t)DI*DTR*2;
constexpr size_t O_YBH  = O_DTWL + (size_t)DI*DTR*2;
constexpr size_t O_YBL  = O_YBH  + (size_t)TOK*DI*2;
constexpr size_t O_OWH  = O_YBL  + (size_t)TOK*DI*2;
constexpr size_t O_OWL  = O_OWH  + (size_t)DD*DI*2;
constexpr size_t O_HMH  = O_OWL  + (size_t)DD*DI*2;
constexpr size_t O_HML  = O_HMH  + (size_t)TOK*DD*2;
constexpr size_t O_W1H  = O_HML  + (size_t)TOK*DD*2;
constexpr size_t O_W1L  = O_W1H  + (size_t)NE*DFF*DD*2;
constexpr size_t O_W2H  = O_W1L  + (size_t)NE*DFF*DD*2;
constexpr size_t O_W2L  = O_W2H  + (size_t)NE*DD*DFF*2;
constexpr size_t O_H1H  = O_W2L  + (size_t)NE*DD*DFF*2;
constexpr size_t O_H1L  = O_H1H  + (size_t)NE*CAP*DFF*2;
constexpr size_t O_HEND = O_H1L  + (size_t)NE*CAP*DFF*2;
constexpr size_t O_HIN  = O_HEND + (size_t)BATCH*NCHUNK*DI*NSTATE*4;
constexpr size_t O_SDT  = O_HIN  + (size_t)BATCH*NCHUNK*DI*NSTATE*4;
constexpr size_t SCRATCH_BYTES = O_SDT + (size_t)BATCH*NCHUNK*DI*4;

__device__ __align__(256) unsigned char g_scratch[SCRATCH_BYTES];
__device__ int   g_cnt[NE];
__device__ int   g_list[NE * CAP];
__device__ int   g_slot[TOK * 2];
__device__ float g_wgt[TOK * 2];

// ---------------- side stream + events (created once, pre-checkpoint) --------
struct StreamCtx {
    cudaStream_t s2;
    cudaEvent_t ev[5];
    StreamCtx() {
        cudaStreamCreateWithFlags(&s2, cudaStreamNonBlocking);
        for (int i = 0; i < 5; i++)
            cudaEventCreateWithFlags(&ev[i], cudaEventDisableTiming);
    }
};
static StreamCtx g_sc;

// ---------------- PTX helpers ----------------
__device__ __forceinline__ uint32_t smem_u32(const void* p) {
    uint32_t a;
    asm("{ .reg .u64 t; cvta.to.shared.u64 t, %1; cvt.u32.u64 %0, t; }" : "=r"(a) : "l"(p));
    return a;
}
__device__ __forceinline__ void cpa16(uint32_t dst, const void* src, bool valid) {
    int sz = valid ? 16 : 0;
    asm volatile("cp.async.ca.shared.global [%0], [%1], 16, %2;"
                 :: "r"(dst), "l"(src), "r"(sz) : "memory");
}
#define CP_COMMIT() asm volatile("cp.async.commit_group;" ::: "memory")
#define CP_WAIT1()  asm volatile("cp.async.wait_group 1;" ::: "memory")

__device__ __forceinline__ void ldsm_x4(uint32_t* r, uint32_t addr) {
    asm volatile("ldmatrix.sync.aligned.m8n8.x4.shared.b16 {%0,%1,%2,%3}, [%4];"
                 : "=r"(r[0]), "=r"(r[1]), "=r"(r[2]), "=r"(r[3]) : "r"(addr));
}
__device__ __forceinline__ void mma16816(float* c, const uint32_t* a, const uint32_t* b) {
    asm volatile(
        "mma.sync.aligned.m16n8k16.row.col.f32.bf16.bf16.f32 "
        "{%0,%1,%2,%3}, {%4,%5,%6,%7}, {%8,%9}, {%0,%1,%2,%3};"
        : "+f"(c[0]), "+f"(c[1]), "+f"(c[2]), "+f"(c[3])
        : "r"(a[0]), "r"(a[1]), "r"(a[2]), "r"(a[3]), "r"(b[0]), "r"(b[1]));
}

__device__ __forceinline__ void split2bf(float v, __nv_bfloat16& h, __nv_bfloat16& l) {
    h = __float2bfloat16(v);
    l = __float2bfloat16(v - __bfloat162float(h));
}

// ---------------- vectorized fp32 -> bf16 hi/lo split ----------------
__global__ __launch_bounds__(256) void split4_kernel(
    const float* __restrict__ src, int lda, int srcRows,
    __nv_bfloat16* __restrict__ hi, __nv_bfloat16* __restrict__ lo,
    int shift, long long totalVec)
{
    long long v = (long long)blockIdx.x * 256 + threadIdx.x;
    if (v >= totalVec) return;
    int r = (int)(v >> shift);
    int c = ((int)v & ((1 << shift) - 1)) << 2;
    float4 val = make_float4(0.f, 0.f, 0.f, 0.f);
    if (r < srcRows) val = *(const float4*)&src[(size_t)r * lda + c];
    __nv_bfloat16 h0, h1, h2, h3, l0, l1, l2, l3;
    split2bf(val.x, h0, l0); split2bf(val.y, h1, l1);
    split2bf(val.z, h2, l2); split2bf(val.w, h3, l3);
    __nv_bfloat162 ph0 = {h0, h1}, ph1 = {h2, h3};
    __nv_bfloat162 pl0 = {l0, l1}, pl1 = {l2, l3};
    uint2 uh = { *(uint32_t*)&ph0, *(uint32_t*)&ph1 };
    uint2 ul = { *(uint32_t*)&pl0, *(uint32_t*)&pl1 };
    *(uint2*)&hi[v << 2] = uh;
    *(uint2*)&lo[v << 2] = ul;
}

// ---------------- tensor-core GEMM: C[M,N] = A[M,K] @ B[N,K]^T ----------------
#define RS 40
#define TILE_B (128 * RS * 2)
#define STAGE_B (4 * TILE_B)
#define TG_SMEM (2 * STAGE_B)

__global__ __launch_bounds__(256) void tgemm(
    const __nv_bfloat16* __restrict__ Ahi, const __nv_bfloat16* __restrict__ Alo,
    int lda, unsigned long long sA,
    const __nv_bfloat16* __restrict__ Bhi, const __nv_bfloat16* __restrict__ Blo,
    int ldb, unsigned long long sB,
    float* __restrict__ C, int ldc, unsigned long long sC,
    __nv_bfloat16* __restrict__ Chi, __nv_bfloat16* __restrict__ Clo,
    int Mfixed, int Nreal, int K,
    const float* __restrict__ bias, int sBias,
    const float* __restrict__ resid,
    int act, int gather, int useCnt, int kSplit)
{
    extern __shared__ char sm[];
    int tid = threadIdx.x, wid = tid >> 5, lane = tid & 31;
    int e  = blockIdx.z / kSplit;
    int ks = blockIdx.z % kSplit;
    int M = useCnt ? g_cnt[e] : Mfixed;
    int m0 = blockIdx.y * 128, n0 = blockIdx.x * 128;
    if (m0 >= M) return;

    uint32_t smb = smem_u32(sm);
    int kLen = K / kSplit;
    int koff0 = ks * kLen;

    int lrow = tid >> 1;
    int half = tid & 1;
    int am = m0 + lrow;
    bool av = am < M;
    size_t arow = gather ? (av ? (size_t)g_list[e * CAP + am] : 0) : (size_t)am;
    const __nv_bfloat16* pAh = Ahi + (size_t)e * sA + arow * (size_t)lda + koff0 + half * 16;
    const __nv_bfloat16* pAl = Alo + (size_t)e * sA + arow * (size_t)lda + koff0 + half * 16;
    const __nv_bfloat16* pBh = Bhi + (size_t)e * sB + (size_t)(n0 + lrow) * ldb + koff0 + half * 16;
    const __nv_bfloat16* pBl = Blo + (size_t)e * sB + (size_t)(n0 + lrow) * ldb + koff0 + half * 16;
    uint32_t dstRow = (uint32_t)(lrow * RS + half * 16) * 2;

    int kTiles = kLen >> 5;

    auto issue_stage = [&](int kt, int stage) {
        uint32_t base = smb + stage * STAGE_B + dstRow;
        int koff = kt << 5;
        cpa16(base,                       pAh + koff,      av);
        cpa16(base + 16,                  pAh + koff + 8,  av);
        cpa16(base + TILE_B,              pAl + koff,      av);
        cpa16(base + TILE_B + 16,         pAl + koff + 8,  av);
        cpa16(base + 2 * TILE_B,          pBh + koff,      true);
        cpa16(base + 2 * TILE_B + 16,     pBh + koff + 8,  true);
        cpa16(base + 3 * TILE_B,          pBl + koff,      true);
        cpa16(base + 3 * TILE_B + 16,     pBl + koff + 8,  true);
        CP_COMMIT();
    };

    float acc[4][4][4] = {};
    int wm = wid >> 2, wn = wid & 3;

    uint32_t aRowSel = (uint32_t)(wm * 64 + (lane & 15)) * RS + ((lane >> 4) << 3);
    uint32_t bRowSel4 = (uint32_t)(wn * 32 + (lane & 7) + ((lane >> 4) << 3)) * RS
                        + (((lane >> 3) & 1) << 3);

    issue_stage(0, 0);

    for (int kt = 0; kt < kTiles; kt++) {
        if (kt + 1 < kTiles) issue_stage(kt + 1, (kt + 1) & 1);
        else CP_COMMIT();
        CP_WAIT1();
        __syncthreads();

        uint32_t stb = smb + (kt & 1) * STAGE_B;
        #pragma unroll
        for (int kk = 0; kk < 2; kk++) {
            uint32_t ah[4][4], al[4][4], bh[4][2], bl[4][2];
            #pragma unroll
            for (int mi = 0; mi < 4; mi++) {
                uint32_t aoff = stb + (aRowSel + (uint32_t)mi * 16 * RS + kk * 16) * 2;
                ldsm_x4(ah[mi], aoff);
                ldsm_x4(al[mi], aoff + TILE_B);
            }
            #pragma unroll
            for (int nj = 0; nj < 2; nj++) {
                uint32_t boff = stb + 2 * TILE_B + (bRowSel4 + (uint32_t)nj * 16 * RS + kk * 16) * 2;
                ldsm_x4(&bh[nj * 2][0], boff);
                ldsm_x4(&bl[nj * 2][0], boff + TILE_B);
            }
            #pragma unroll
            for (int mi = 0; mi < 4; mi++)
                #pragma unroll
                for (int ni = 0; ni < 4; ni++) {
                    mma16816(acc[mi][ni], ah[mi], bh[ni]);
                    mma16816(acc[mi][ni], ah[mi], bl[ni]);
                    mma16816(acc[mi][ni], al[mi], bh[ni]);
                }
        }
        __syncthreads();
    }

    // ---- epilogue ----
    int r0 = lane >> 2, c0 = (lane & 3) << 1;
    const float* bp = bias ? bias + (size_t)e * sBias : nullptr;
    #pragma unroll
    for (int mi = 0; mi < 4; mi++) {
        #pragma unroll
        for (int q2 = 0; q2 < 2; q2++) {
            int m = m0 + wm * 64 + mi * 16 + r0 + q2 * 8;
            if (m >= M) continue;
            size_t rowoff = (size_t)e * sC + (size_t)m * ldc;
            size_t resoff = (size_t)m * ldc;
            #pragma unroll
            for (int ni = 0; ni < 4; ni++) {
                int n = n0 + wn * 32 + ni * 8 + c0;
                if (n >= Nreal) continue;
                float v0 = acc[mi][ni][q2 * 2 + 0];
                float v1 = acc[mi][ni][q2 * 2 + 1];
                if (bp)    { v0 += bp[n];  v1 += bp[n + 1]; }
                if (resid) { v0 += resid[resoff + n]; v1 += resid[resoff + n + 1]; }
                if (act == 1)      { v0 = v0 / (1.f + __expf(-v0)); v1 = v1 / (1.f + __expf(-v1)); }
                else if (act == 2) { v0 = (v0 > 20.f) ? v0 : log1pf(__expf(v0));
                                     v1 = (v1 > 20.f) ? v1 : log1pf(__expf(v1)); }
                if (kSplit > 1) {
                    atomicAdd(&C[rowoff + n], v0);
                    atomicAdd(&C[rowoff + n + 1], v1);
                } else {
                    if (C) { float2 f2 = {v0, v1}; *(float2*)&C[rowoff + n] = f2; }
                    if (Chi) {
                        __nv_bfloat16 h0, h1, l0, l1;
                        split2bf(v0, h0, l0); split2bf(v1, h1, l1);
                        __nv_bfloat162 ph = {h0, h1}, pl = {l0, l1};
                        *(__nv_bfloat162*)&Chi[rowoff + n] = ph;
                        *(__nv_bfloat162*)&Clo[rowoff + n] = pl;
                    }
                }
            }
        }
    }
}

// ---------------- LayerNorm (fused bf16 hi/lo emission; optional cnt reset) ---
__global__ __launch_bounds__(256) void ln_kernel(
    const float* __restrict__ x, float* __restrict__ outF,
    __nv_bfloat16* __restrict__ outH, __nv_bfloat16* __restrict__ outL,
    const float* __restrict__ g, const float* __restrict__ b,
    int zeroCnt)
{
    if (zeroCnt && blockIdx.x == 0 && threadIdx.x < NE) g_cnt[threadIdx.x] = 0;
    int tok = blockIdx.x;
    int i = threadIdx.x << 2;
    const float* xr = x + (size_t)tok * DD;
    float4 v = *(const float4*)&xr[i];
    float s  = v.x + v.y + v.z + v.w;
    float s2 = v.x*v.x + v.y*v.y + v.z*v.z + v.w*v.w;
    #pragma unroll
    for (int o = 16; o > 0; o >>= 1) {
        s  += __shfl_xor_sync(0xffffffffu, s,  o);
        s2 += __shfl_xor_sync(0xffffffffu, s2, o);
    }
    __shared__ float sh[16];
    int w = threadIdx.x >> 5;
    if ((threadIdx.x & 31) == 0) { sh[w] = s; sh[8 + w] = s2; }
    __syncthreads();
    s = 0.f; s2 = 0.f;
    #pragma unroll
    for (int k = 0; k < 8; k++) { s += sh[k]; s2 += sh[8 + k]; }
    float mu  = s * (1.0f / DD);
    float var = s2 * (1.0f / DD) - mu * mu;
    float rr = rsqrtf(var + 1e-5f);
    float4 gv = *(const float4*)&g[i];
    float4 bv = *(const float4*)&b[i];
    float4 o4;
    o4.x = (v.x - mu) * rr * gv.x + bv.x;
    o4.y = (v.y - mu) * rr * gv.y + bv.y;
    o4.z = (v.z - mu) * rr * gv.z + bv.z;
    o4.w = (v.w - mu) * rr * gv.w + bv.w;
    size_t off = (size_t)tok * DD + i;
    if (outF) *(float4*)&outF[off] = o4;
    __nv_bfloat16 h0,h1,h2,h3,l0,l1,l2,l3;
    split2bf(o4.x,h0,l0); split2bf(o4.y,h1,l1); split2bf(o4.z,h2,l2); split2bf(o4.w,h3,l3);
    __nv_bfloat162 ph0={h0,h1}, ph1={h2,h3}, pl0={l0,l1}, pl1={l2,l3};
    uint2 uh = { *(uint32_t*)&ph0, *(uint32_t*)&ph1 };
    uint2 ul = { *(uint32_t*)&pl0, *(uint32_t*)&pl1 };
    *(uint2*)&outH[off] = uh;
    *(uint2*)&outL[off] = ul;
}

// ---------------- causal depthwise conv (KC=4) + SiLU + proj zero-fill -------
__global__ __launch_bounds__(256) void conv_silu_kernel(
    const float* __restrict__ xz,
    const float* __restrict__ cw,
    const float* __restrict__ cb,
    float* __restrict__ xc,
    __nv_bfloat16* __restrict__ xch,
    __nv_bfloat16* __restrict__ xcl,
    float* __restrict__ projZero)
{
    int idx = blockIdx.x * 256 + threadIdx.x;
    if (idx < (TOK * PROJN) / 4)
        *(float4*)&projZero[(size_t)idx << 2] = make_float4(0.f, 0.f, 0.f, 0.f);
    int d = (idx & 511) << 2;
    int m = idx >> 9;
    int t = m & (TT - 1);
    const float* base = xz + (size_t)m * XZN + d;
    float4 z4 = make_float4(0.f,0.f,0.f,0.f);
    float4 x3 = (t >= 3) ? *(const float4*)(base - 3 * XZN) : z4;
    float4 x2 = (t >= 2) ? *(const float4*)(base - 2 * XZN) : z4;
    float4 x1 = (t >= 1) ? *(const float4*)(base - XZN) : z4;
    float4 x0 = *(const float4*)base;
    float4 cbv = *(const float4*)&cb[d];
    float4 w0 = *(const float4*)&cw[(d + 0) * 4];
    float4 w1 = *(const float4*)&cw[(d + 1) * 4];
    float4 w2 = *(const float4*)&cw[(d + 2) * 4];
    float4 w3 = *(const float4*)&cw[(d + 3) * 4];
    float4 a;
    a.x = cbv.x + w0.x*x3.x + w0.y*x2.x + w0.z*x1.x + w0.w*x0.x;
    a.y = cbv.y + w1.x*x3.y + w1.y*x2.y + w1.z*x1.y + w1.w*x0.y;
    a.z = cbv.z + w2.x*x3.z + w2.y*x2.z + w2.z*x1.z + w2.w*x0.z;
    a.w = cbv.w + w3.x*x3.w + w3.y*x2.w + w3.z*x1.w + w3.w*x0.w;
    a.x = a.x / (1.f + __expf(-a.x));
    a.y = a.y / (1.f + __expf(-a.y));
    a.z = a.z / (1.f + __expf(-a.z));
    a.w = a.w / (1.f + __expf(-a.w));
    size_t off = (size_t)m * DI + d;
    *(float4*)&xc[off] = a;
    __nv_bfloat16 h0,h1,h2,h3,l0,l1,l2,l3;
    split2bf(a.x,h0,l0); split2bf(a.y,h1,l1); split2bf(a.z,h2,l2); split2bf(a.w,h3,l3);
    __nv_bfloat162 ph0={h0,h1}, ph1={h2,h3}, pl0={l0,l1}, pl1={l2,l3};
    uint2 uh = { *(uint32_t*)&ph0, *(uint32_t*)&ph1 };
    uint2 ul = { *(uint32_t*)&pl0, *(uint32_t*)&pl1 };
    *(uint2*)&xch[off] = uh;
    *(uint2*)&xcl[off] = ul;
}

// ---------------- blocked selective scan ----------------
__global__ __launch_bounds__(256) void scan1_kernel(
    const float* __restrict__ proj,
    const float* __restrict__ xc,
    const float* __restrict__ dt,
    const float* __restrict__ A_log,
    float* __restrict__ hend,
    float* __restrict__ sumdt)
{
    int b = blockIdx.z, chunk = blockIdx.y;
    int lane = threadIdx.x & 31;
    int ch = lane >> 2, ng = lane & 3;
    int d = (blockIdx.x * 8 + (threadIdx.x >> 5)) * 8 + ch;

    float4 Al = *(const float4*)&A_log[(size_t)d * NSTATE + ng * 4];
    float a0 = -__expf(Al.x), a1 = -__expf(Al.y), a2 = -__expf(Al.z), a3 = -__expf(Al.w);
    float h0 = 0.f, h1 = 0.f, h2 = 0.f, h3 = 0.f, sdt = 0.f;
    size_t tokbase = (size_t)b * TT + (size_t)chunk * CL;

    for (int t = 0; t < CL; t++) {
        size_t tok = tokbase + t;
        float4 Bv = *(const float4*)&proj[tok * PROJN + DTR + ng * 4];
        float xt  = xc[tok * DI + d];
        float dtt = dt[tok * DI + d];
        sdt += dtt;
        float dx = dtt * xt;
        h0 = __expf(dtt * a0) * h0 + dx * Bv.x;
        h1 = __expf(dtt * a1) * h1 + dx * Bv.y;
        h2 = __expf(dtt * a2) * h2 + dx * Bv.z;
        h3 = __expf(dtt * a3) * h3 + dx * Bv.w;
    }
    size_t cdi = ((size_t)(b * NCHUNK + chunk) * DI + d);
    float4 hv = {h0, h1, h2, h3};
    *(float4*)&hend[cdi * NSTATE + ng * 4] = hv;
    if (ng == 0) sumdt[cdi] = sdt;
}

__global__ __launch_bounds__(256) void scomb_kernel(
    const float* __restrict__ A_log,
    const float* __restrict__ hend,
    const float* __restrict__ sumdt,
    float* __restrict__ hin)
{
    int idx = blockIdx.x * 256 + threadIdx.x;
    int n = idx & (NSTATE - 1);
    int d = (idx >> 4) & (DI - 1);
    int b = idx >> 15;
    float a = -__expf(A_log[(size_t)d * NSTATE + n]);
    float h = 0.f;
    #pragma unroll
    for (int c = 0; c < NCHUNK; c++) {
        size_t cdi = (size_t)(b * NCHUNK + c) * DI + d;
        hin[cdi * NSTATE + n] = h;
        h = __expf(a * sumdt[cdi]) * h + hend[cdi * NSTATE + n];
    }
}

__global__ __launch_bounds__(256) void scan2_kernel(
    const float* __restrict__ proj,
    const float* __restrict__ xc,
    const float* __restrict__ dt,
    const float* __restrict__ xz,
    const float* __restrict__ A_log,
    const float* __restrict__ D_skip,
    const float* __restrict__ hin,
    __nv_bfloat16* __restrict__ ybh,
    __nv_bfloat16* __restrict__ ybl)
{
    int b = blockIdx.z, chunk = blockIdx.y;
    int lane = threadIdx.x & 31;
    int ch = lane >> 2, ng = lane & 3;
    int d = (blockIdx.x * 8 + (threadIdx.x >> 5)) * 8 + ch;

    float4 Al = *(const float4*)&A_log[(size_t)d * NSTATE + ng * 4];
    float a0 = -__expf(Al.x), a1 = -__expf(Al.y), a2 = -__expf(Al.z), a3 = -__expf(Al.w);
    size_t cdi = (size_t)(b * NCHUNK + chunk) * DI + d;
    float4 hv = *(const float4*)&hin[cdi * NSTATE + ng * 4];
    float h0 = hv.x, h1 = hv.y, h2 = hv.z, h3 = hv.w;
    float dsk = D_skip[d];
    size_t tokbase = (size_t)b * TT + (size_t)chunk * CL;

    for (int t = 0; t < CL; t++) {
        size_t tok = tokbase + t;
        float4 Bv = *(const float4*)&proj[tok * PROJN + DTR + ng * 4];
        float4 Cv = *(const float4*)&proj[tok * PROJN + DTR + NSTATE + ng * 4];
        float xt  = xc[tok * DI + d];
        float dtt = dt[tok * DI + d];
        float dx = dtt * xt;
        h0 = __expf(dtt * a0) * h0 + dx * Bv.x;
        h1 = __expf(dtt * a1) * h1 + dx * Bv.y;
        h2 = __expf(dtt * a2) * h2 + dx * Bv.z;
        h3 = __expf(dtt * a3) * h3 + dx * Bv.w;
        float y = h0 * Cv.x + h1 * Cv.y + h2 * Cv.z + h3 * Cv.w;
        y += __shfl_xor_sync(0xffffffffu, y, 1);
        y += __shfl_xor_sync(0xffffffffu, y, 2);
        if (ng == 0) {
            float z = xz[tok * XZN + DI + d];
            float sil = z / (1.f + __expf(-z));
            float v = (y + xt * dsk) * sil;
            __nv_bfloat16 hh, ll;
            split2bf(v, hh, ll);
            ybh[tok * DI + d] = hh;
            ybl[tok * DI + d] = ll;
        }
    }
}

// ---------------- router: softmax + top2 + expert list build ----------------
__global__ __launch_bounds__(256) void router_kernel(
    const float* __restrict__ xin,
    const float* __restrict__ rw,
    float* __restrict__ probs_out)
{
    int warp = threadIdx.x >> 5, lane = threadIdx.x & 31;
    int tok = blockIdx.x * 8 + warp;
    const float* xr = xin + (size_t)tok * DD;
    float acc[8] = {};
    for (int c = lane; c < DD; c += 32) {
        float xv = xr[c];
        #pragma unroll
        for (int e = 0; e < 8; e++) acc[e] += xv * rw[e * DD + c];
    }
    #pragma unroll
    for (int e = 0; e < 8; e++)
        #pragma unroll
        for (int o = 16; o > 0; o >>= 1) acc[e] += __shfl_xor_sync(0xffffffffu, acc[e], o);
    if (lane == 0) {
        float mx = acc[0];
        #pragma unroll
        for (int e = 1; e < 8; e++) mx = fmaxf(mx, acc[e]);
        float p[8], s = 0.f;
        #pragma unroll
        for (int e = 0; e < 8; e++) { p[e] = __expf(acc[e] - mx); s += p[e]; }
        float inv = 1.f / s;
        #pragma unroll
        for (int e = 0; e < 8; e++) { p[e] *= inv; probs_out[(size_t)tok * 8 + e] = p[e]; }
        int i0 = 0; float v0 = p[0];
        #pragma unroll
        for (int e = 1; e < 8; e++) if (p[e] > v0) { v0 = p[e]; i0 = e; }
        int i1 = -1; float v1 = -1.f;
        #pragma unroll
        for (int e = 0; e < 8; e++) if (e != i0 && p[e] > v1) { v1 = p[e]; i1 = e; }
        float wn = 1.f / (v0 + v1);
        int p0 = atomicAdd(&g_cnt[i0], 1);
        int p1 = atomicAdd(&g_cnt[i1], 1);
        g_list[i0 * CAP + p0] = tok;
        g_list[i1 * CAP + p1] = tok;
        g_slot[tok * 2 + 0] = i0 * CAP + p0;
        g_slot[tok * 2 + 1] = i1 * CAP + p1;
        g_wgt[tok * 2 + 0] = v0 * wn;
        g_wgt[tok * 2 + 1] = v1 * wn;
    }
}

// ---------------- combine ----------------
__global__ __launch_bounds__(256) void combine_kernel(float* __restrict__ hout,
                                                      const float* __restrict__ ye)
{
    int tok = blockIdx.x;
    int j = threadIdx.x << 2;
    int s0 = g_slot[tok * 2], s1 = g_slot[tok * 2 + 1];
    float w0 = g_wgt[tok * 2], w1 = g_wgt[tok * 2 + 1];
    float4 a  = *(float4*)&hout[(size_t)tok * DD + j];
    float4 y0 = *(const float4*)&ye[(size_t)s0 * DD + j];
    float4 y1 = *(const float4*)&ye[(size_t)s1 * DD + j];
    a.x += w0 * y0.x + w1 * y1.x;
    a.y += w0 * y0.y + w1 * y1.y;
    a.z += w0 * y0.z + w1 * y1.z;
    a.w += w0 * y0.w + w1 * y1.w;
    *(float4*)&hout[(size_t)tok * DD + j] = a;
}

// ---------------- launcher ----------------
static inline int vblk(long long totalVec) { return (int)((totalVec + 255) / 256); }

extern "C" void kernel_launch(void* const* d_in, const int* in_sizes, int n_in,
                              void* d_out, int out_size)
{
    const float* x        = (const float*)d_in[0];
    const float* lnm_g    = (const float*)d_in[1];
    const float* lnm_b    = (const float*)d_in[2];
    const float* lne_g    = (const float*)d_in[3];
    const float* lne_b    = (const float*)d_in[4];
    const float* in_w     = (const float*)d_in[5];
    const float* in_b     = (const float*)d_in[6];
    const float* conv_w   = (const float*)d_in[7];
    const float* conv_b   = (const float*)d_in[8];
    const float* xproj_w  = (const float*)d_in[9];
    const float* dt_w     = (const float*)d_in[10];
    const float* dt_b     = (const float*)d_in[11];
    const float* A_log    = (const float*)d_in[12];
    const float* D_skip   = (const float*)d_in[13];
    const float* out_w    = (const float*)d_in[14];
    const float* router_w = (const float*)d_in[15];
    const float* w1       = (const float*)d_in[16];
    const float* b1       = (const float*)d_in[17];
    const float* w2       = (const float*)d_in[18];
    const float* b2       = (const float*)d_in[19];

    float* out_h     = (float*)d_out;
    float* out_probs = out_h + (size_t)TOK * DD;

    unsigned char* S;
    cudaGetSymbolAddress((void**)&S, g_scratch);
    float* xz    = (float*)(S + O_XZ);
    float* xc    = (float*)(S + O_XC);
    float* proj  = (float*)(S + O_PROJ);
    float* dtb   = (float*)(S + O_DT);
    float* hm    = (float*)(S + O_HM);
    float* ye    = (float*)(S + O_YE);
    float* hend  = (float*)(S + O_HEND);
    float* hin   = (float*)(S + O_HIN);
    float* sdt   = (float*)(S + O_SDT);
    __nv_bfloat16* hnh  = (__nv_bfloat16*)(S + O_HNH);
    __nv_bfloat16* hnl  = (__nv_bfloat16*)(S + O_HNL);
    __nv_bfloat16* inwh = (__nv_bfloat16*)(S + O_INWH);
    __nv_bfloat16* inwl = (__nv_bfloat16*)(S + O_INWL);
    __nv_bfloat16* xch  = (__nv_bfloat16*)(S + O_XCH);
    __nv_bfloat16* xcl  = (__nv_bfloat16*)(S + O_XCL);
    __nv_bfloat16* xpwh = (__nv_bfloat16*)(S + O_XPWH);
    __nv_bfloat16* xpwl = (__nv_bfloat16*)(S + O_XPWL);
    __nv_bfloat16* dtah = (__nv_bfloat16*)(S + O_DTAH);
    __nv_bfloat16* dtal = (__nv_bfloat16*)(S + O_DTAL);
    __nv_bfloat16* dtwh = (__nv_bfloat16*)(S + O_DTWH);
    __nv_bfloat16* dtwl = (__nv_bfloat16*)(S + O_DTWL);
    __nv_bfloat16* ybh  = (__nv_bfloat16*)(S + O_YBH);
    __nv_bfloat16* ybl  = (__nv_bfloat16*)(S + O_YBL);
    __nv_bfloat16* owh  = (__nv_bfloat16*)(S + O_OWH);
    __nv_bfloat16* owl  = (__nv_bfloat16*)(S + O_OWL);
    __nv_bfloat16* hmh  = (__nv_bfloat16*)(S + O_HMH);
    __nv_bfloat16* hml  = (__nv_bfloat16*)(S + O_HML);
    __nv_bfloat16* w1h  = (__nv_bfloat16*)(S + O_W1H);
    __nv_bfloat16* w1l  = (__nv_bfloat16*)(S + O_W1L);
    __nv_bfloat16* w2h  = (__nv_bfloat16*)(S + O_W2H);
    __nv_bfloat16* w2l  = (__nv_bfloat16*)(S + O_W2L);
    __nv_bfloat16* h1h  = (__nv_bfloat16*)(S + O_H1H);
    __nv_bfloat16* h1l  = (__nv_bfloat16*)(S + O_H1L);

    cudaFuncSetAttribute(tgemm, cudaFuncAttributeMaxDynamicSharedMemorySize, TG_SMEM);

    cudaStream_t s2 = g_sc.s2;
    cudaEvent_t* ev = g_sc.ev;

    // ---- fork side stream: all weight splits (depend only on inputs) ----
    cudaEventRecord(ev[0], 0);
    cudaStreamWaitEvent(s2, ev[0], 0);
    split4_kernel<<<vblk((long long)XZN*DD/4), 256, 0, s2>>>(in_w, DD, XZN, inwh, inwl, 8, (long long)XZN*DD/4);
    cudaEventRecord(ev[1], s2);
    split4_kernel<<<vblk((long long)128*DI/4), 256, 0, s2>>>(xproj_w, DI, PROJN, xpwh, xpwl, 9, (long long)128*DI/4);
    split4_kernel<<<vblk((long long)DI*DTR/4), 256, 0, s2>>>(dt_w, DTR, DI, dtwh, dtwl, 4, (long long)DI*DTR/4);
    cudaEventRecord(ev[2], s2);
    split4_kernel<<<vblk((long long)DD*DI/4), 256, 0, s2>>>(out_w, DI, DD, owh, owl, 9, (long long)DD*DI/4);
    cudaEventRecord(ev[3], s2);
    split4_kernel<<<vblk((long long)NE*DFF*DD/4), 256, 0, s2>>>(w1, DD, NE*DFF, w1h, w1l, 8, (long long)NE*DFF*DD/4);
    split4_kernel<<<vblk((long long)NE*DD*DFF/4), 256, 0, s2>>>(w2, DFF, NE*DD, w2h, w2l, 9, (long long)NE*DD*DFF/4);
    cudaEventRecord(ev[4], s2);

    // ---- main chain ----
    // 1. LN (mamba) -> hi/lo only
    ln_kernel<<<TOK, 256>>>(x, nullptr, hnh, hnl, lnm_g, lnm_b, 0);
    // 2. in_proj (needs in_w split)
    cudaStreamWaitEvent(0, ev[1], 0);
    tgemm<<<dim3(XZN/128, TOK/128, 1), 256, TG_SMEM>>>(
        hnh, hnl, DD, 0, inwh, inwl, DD, 0,
        xz, XZN, 0, nullptr, nullptr,
        TOK, XZN, DD, in_b, 0, nullptr, 0, 0, 0, 1);
    // 3. conv + silu (+ zero proj)
    conv_silu_kernel<<<(TOK*DI/4)/256, 256>>>(xz, conv_w, conv_b, xc, xch, xcl, proj);
    // 4. x_proj split-K=8 (needs xpw split)
    cudaStreamWaitEvent(0, ev[2], 0);
    tgemm<<<dim3(1, TOK/128, 8), 256, TG_SMEM>>>(
        xch, xcl, DI, 0, xpwh, xpwl, DI, 0,
        proj, PROJN, 0, nullptr, nullptr,
        TOK, PROJN, DI, nullptr, 0, nullptr, 0, 0, 0, 8);
    // 5. dt_r split (needs proj)
    split4_kernel<<<vblk((long long)TOK*DTR/4), 256>>>(proj, PROJN, TOK, dtah, dtal, 4, (long long)TOK*DTR/4);
    // 6. dt_proj
    tgemm<<<dim3(DI/128, TOK/128, 1), 256, TG_SMEM>>>(
        dtah, dtal, DTR, 0, dtwh, dtwl, DTR, 0,
        dtb, DI, 0, nullptr, nullptr,
        TOK, DI, DTR, dt_b, 0, nullptr, 2, 0, 0, 1);
    // 7. blocked selective scan (NCHUNK=128)
    scan1_kernel<<<dim3(32, NCHUNK, BATCH), 256>>>(proj, xc, dtb, A_log, hend, sdt);
    scomb_kernel<<<(BATCH*DI*NSTATE)/256, 256>>>(A_log, hend, sdt, hin);
    scan2_kernel<<<dim3(32, NCHUNK, BATCH), 256>>>(proj, xc, dtb, xz, A_log, D_skip, hin, ybh, ybl);
    // 8. out_proj + residual (needs out_w split)
    cudaStreamWaitEvent(0, ev[3], 0);
    tgemm<<<dim3(DD/128, TOK/128, 1), 256, TG_SMEM>>>(
        ybh, ybl, DI, 0, owh, owl, DI, 0,
        out_h, DD, 0, nullptr, nullptr,
        TOK, DD, DI, nullptr, 0, x, 0, 0, 0, 1);
    // 9. LN (moe) + g_cnt reset
    ln_kernel<<<TOK, 256>>>(out_h, hm, hmh, hml, lne_g, lne_b, 1);
    // 10. router
    router_kernel<<<TOK/8, 256>>>(hm, router_w, out_probs);
    // 11. expert GEMM 1 (needs w1/w2 splits)
    cudaStreamWaitEvent(0, ev[4], 0);
    tgemm<<<dim3(DFF/128, CAP/128, NE), 256, TG_SMEM>>>(
        hmh, hml, DD, 0, w1h, w1l, DD, (unsigned long long)DFF*DD,
        nullptr, DFF, (unsigned long long)CAP*DFF, h1h, h1l,
        0, DFF, DD, b1, DFF, nullptr, 1, 1, 1, 1);
    // 12. expert GEMM 2
    tgemm<<<dim3(DD/128, CAP/128, NE), 256, TG_SMEM>>>(
        h1h, h1l, DFF, (unsigned long long)CAP*DFF, w2h, w2l, DFF, (unsigned long long)DD*DFF,
        ye, DD, (unsigned long long)CAP*DD, nullptr, nullptr,
        0, DD, DFF, b2, DD, nullptr, 0, 0, 1, 1);
    // 13. combine
    combine_kernel<<<TOK, 256>>>(out_h, ye);
}

// round 15
// speedup vs baseline: 1.0093x; 1.0093x over previous
#include <cuda_runtime.h>
#include <cuda_bf16.h>
#include <cstdint>
#include <math.h>

// ---------------- problem constants ----------------
#define BATCH 2
#define TT    2048
#define TOK   4096          // BATCH*TT
#define DD    1024
#define DI    2048
#define XZN   4096          // 2*DI
#define NSTATE 16
#define DTR   64
#define PROJN 96            // DTR + 2*NSTATE
#define DFF   2048
#define NE    8
#define CAP   4096          // max tokens per expert
#define NCHUNK 64
#define CL    (TT / NCHUNK) // 32

// ---------------- unified scratch (single symbol; no allocs) ----------------
constexpr size_t O_XZ   = 0;
constexpr size_t O_XC   = O_XZ   + (size_t)TOK*XZN*4;
constexpr size_t O_PROJ = O_XC   + (size_t)TOK*DI*4;
constexpr size_t O_DT   = O_PROJ + (size_t)TOK*PROJN*4;
constexpr size_t O_YE   = O_DT   + (size_t)TOK*DI*4;
constexpr size_t O_HNH  = O_YE   + (size_t)NE*CAP*DD*4;
constexpr size_t O_HNL  = O_HNH  + (size_t)TOK*DD*2;
constexpr size_t O_INWH = O_HNL  + (size_t)TOK*DD*2;
constexpr size_t O_INWL = O_INWH + (size_t)XZN*DD*2;
constexpr size_t O_XCH  = O_INWL + (size_t)XZN*DD*2;
constexpr size_t O_XCL  = O_XCH  + (size_t)TOK*DI*2;
constexpr size_t O_XPWH = O_XCL  + (size_t)TOK*DI*2;
constexpr size_t O_XPWL = O_XPWH + (size_t)128*DI*2;
constexpr size_t O_DTAH = O_XPWL + (size_t)128*DI*2;
constexpr size_t O_DTAL = O_DTAH + (size_t)TOK*DTR*2;
constexpr size_t O_DTWH = O_DTAL + (size_t)TOK*DTR*2;
constexpr size_t O_DTWL = O_DTWH + (size_t)DI*DTR*2;
constexpr size_t O_YBH  = O_DTWL + (size_t)DI*DTR*2;
constexpr size_t O_YBL  = O_YBH  + (size_t)TOK*DI*2;
constexpr size_t O_OWH  = O_YBL  + (size_t)TOK*DI*2;
constexpr size_t O_OWL  = O_OWH  + (size_t)DD*DI*2;
constexpr size_t O_HMH  = O_OWL  + (size_t)DD*DI*2;
constexpr size_t O_HML  = O_HMH  + (size_t)TOK*DD*2;
constexpr size_t O_W1H  = O_HML  + (size_t)TOK*DD*2;
constexpr size_t O_W1L  = O_W1H  + (size_t)NE*DFF*DD*2;
constexpr size_t O_W2H  = O_W1L  + (size_t)NE*DFF*DD*2;
constexpr size_t O_W2L  = O_W2H  + (size_t)NE*DD*DFF*2;
constexpr size_t O_H1H  = O_W2L  + (size_t)NE*DD*DFF*2;
constexpr size_t O_H1L  = O_H1H  + (size_t)NE*CAP*DFF*2;
constexpr size_t O_HEND = O_H1L  + (size_t)NE*CAP*DFF*2;
constexpr size_t O_HIN  = O_HEND + (size_t)BATCH*NCHUNK*DI*NSTATE*4;
constexpr size_t O_SDT  = O_HIN  + (size_t)BATCH*NCHUNK*DI*NSTATE*4;
constexpr size_t SCRATCH_BYTES = O_SDT + (size_t)BATCH*NCHUNK*DI*4;

__device__ __align__(256) unsigned char g_scratch[SCRATCH_BYTES];
__device__ int   g_cnt[NE];
__device__ int   g_list[NE * CAP];
__device__ int   g_slot[TOK * 2];
__device__ float g_wgt[TOK * 2];

// ---------------- side stream + events (created once, pre-checkpoint) --------
struct StreamCtx {
    cudaStream_t s2;
    cudaEvent_t ev[5];
    StreamCtx() {
        cudaStreamCreateWithFlags(&s2, cudaStreamNonBlocking);
        for (int i = 0; i < 5; i++)
            cudaEventCreateWithFlags(&ev[i], cudaEventDisableTiming);
    }
};
static StreamCtx g_sc;

// ---------------- PTX helpers ----------------
__device__ __forceinline__ uint32_t smem_u32(const void* p) {
    uint32_t a;
    asm("{ .reg .u64 t; cvta.to.shared.u64 t, %1; cvt.u32.u64 %0, t; }" : "=r"(a) : "l"(p));
    return a;
}
__device__ __forceinline__ void cpa16(uint32_t dst, const void* src, bool valid) {
    int sz = valid ? 16 : 0;
    asm volatile("cp.async.ca.shared.global [%0], [%1], 16, %2;"
                 :: "r"(dst), "l"(src), "r"(sz) : "memory");
}
#define CP_COMMIT() asm volatile("cp.async.commit_group;" ::: "memory")
#define CP_WAIT1()  asm volatile("cp.async.wait_group 1;" ::: "memory")

__device__ __forceinline__ void ldsm_x4(uint32_t* r, uint32_t addr) {
    asm volatile("ldmatrix.sync.aligned.m8n8.x4.shared.b16 {%0,%1,%2,%3}, [%4];"
                 : "=r"(r[0]), "=r"(r[1]), "=r"(r[2]), "=r"(r[3]) : "r"(addr));
}
__device__ __forceinline__ void mma16816(float* c, const uint32_t* a, const uint32_t* b) {
    asm volatile(
        "mma.sync.aligned.m16n8k16.row.col.f32.bf16.bf16.f32 "
        "{%0,%1,%2,%3}, {%4,%5,%6,%7}, {%8,%9}, {%0,%1,%2,%3};"
        : "+f"(c[0]), "+f"(c[1]), "+f"(c[2]), "+f"(c[3])
        : "r"(a[0]), "r"(a[1]), "r"(a[2]), "r"(a[3]), "r"(b[0]), "r"(b[1]));
}

__device__ __forceinline__ void split2bf(float v, __nv_bfloat16& h, __nv_bfloat16& l) {
    h = __float2bfloat16(v);
    l = __float2bfloat16(v - __bfloat162float(h));
}

// ---------------- vectorized fp32 -> bf16 hi/lo split ----------------
__global__ __launch_bounds__(256) void split4_kernel(
    const float* __restrict__ src, int lda, int srcRows,
    __nv_bfloat16* __restrict__ hi, __nv_bfloat16* __restrict__ lo,
    int shift, long long totalVec)
{
    long long v = (long long)blockIdx.x * 256 + threadIdx.x;
    if (v >= totalVec) return;
    int r = (int)(v >> shift);
    int c = ((int)v & ((1 << shift) - 1)) << 2;
    float4 val = make_float4(0.f, 0.f, 0.f, 0.f);
    if (r < srcRows) val = *(const float4*)&src[(size_t)r * lda + c];
    __nv_bfloat16 h0, h1, h2, h3, l0, l1, l2, l3;
    split2bf(val.x, h0, l0); split2bf(val.y, h1, l1);
    split2bf(val.z, h2, l2); split2bf(val.w, h3, l3);
    __nv_bfloat162 ph0 = {h0, h1}, ph1 = {h2, h3};
    __nv_bfloat162 pl0 = {l0, l1}, pl1 = {l2, l3};
    uint2 uh = { *(uint32_t*)&ph0, *(uint32_t*)&ph1 };
    uint2 ul = { *(uint32_t*)&pl0, *(uint32_t*)&pl1 };
    *(uint2*)&hi[v << 2] = uh;
    *(uint2*)&lo[v << 2] = ul;
}

// ---------------- tensor-core GEMM: C[M,N] = A[M,K] @ B[N,K]^T ----------------
#define RS 40
#define TILE_B (128 * RS * 2)
#define STAGE_B (4 * TILE_B)
#define TG_SMEM (2 * STAGE_B)

__global__ __launch_bounds__(256) void tgemm(
    const __nv_bfloat16* __restrict__ Ahi, const __nv_bfloat16* __restrict__ Alo,
    int lda, unsigned long long sA,
    const __nv_bfloat16* __restrict__ Bhi, const __nv_bfloat16* __restrict__ Blo,
    int ldb, unsigned long long sB,
    float* __restrict__ C, int ldc, unsigned long long sC,
    __nv_bfloat16* __restrict__ Chi, __nv_bfloat16* __restrict__ Clo,
    int Mfixed, int Nreal, int K,
    const float* __restrict__ bias, int sBias,
    const float* __restrict__ resid,
    int act, int gather, int useCnt, int kSplit)
{
    extern __shared__ char sm[];
    int tid = threadIdx.x, wid = tid >> 5, lane = tid & 31;
    int e  = blockIdx.z / kSplit;
    int ks = blockIdx.z % kSplit;
    int M = useCnt ? g_cnt[e] : Mfixed;
    int m0 = blockIdx.y * 128, n0 = blockIdx.x * 128;
    if (m0 >= M) return;

    uint32_t smb = smem_u32(sm);
    int kLen = K / kSplit;
    int koff0 = ks * kLen;

    int lrow = tid >> 1;
    int half = tid & 1;
    int am = m0 + lrow;
    bool av = am < M;
    size_t arow = gather ? (av ? (size_t)g_list[e * CAP + am] : 0) : (size_t)am;
    const __nv_bfloat16* pAh = Ahi + (size_t)e * sA + arow * (size_t)lda + koff0 + half * 16;
    const __nv_bfloat16* pAl = Alo + (size_t)e * sA + arow * (size_t)lda + koff0 + half * 16;
    const __nv_bfloat16* pBh = Bhi + (size_t)e * sB + (size_t)(n0 + lrow) * ldb + koff0 + half * 16;
    const __nv_bfloat16* pBl = Blo + (size_t)e * sB + (size_t)(n0 + lrow) * ldb + koff0 + half * 16;
    uint32_t dstRow = (uint32_t)(lrow * RS + half * 16) * 2;

    int kTiles = kLen >> 5;

    auto issue_stage = [&](int kt, int stage) {
        uint32_t base = smb + stage * STAGE_B + dstRow;
        int koff = kt << 5;
        cpa16(base,                       pAh + koff,      av);
        cpa16(base + 16,                  pAh + koff + 8,  av);
        cpa16(base + TILE_B,              pAl + koff,      av);
        cpa16(base + TILE_B + 16,         pAl + koff + 8,  av);
        cpa16(base + 2 * TILE_B,          pBh + koff,      true);
        cpa16(base + 2 * TILE_B + 16,     pBh + koff + 8,  true);
        cpa16(base + 3 * TILE_B,          pBl + koff,      true);
        cpa16(base + 3 * TILE_B + 16,     pBl + koff + 8,  true);
        CP_COMMIT();
    };

    float acc[4][4][4] = {};
    int wm = wid >> 2, wn = wid & 3;

    uint32_t aRowSel = (uint32_t)(wm * 64 + (lane & 15)) * RS + ((lane >> 4) << 3);
    uint32_t bRowSel4 = (uint32_t)(wn * 32 + (lane & 7) + ((lane >> 4) << 3)) * RS
                        + (((lane >> 3) & 1) << 3);

    issue_stage(0, 0);

    for (int kt = 0; kt < kTiles; kt++) {
        if (kt + 1 < kTiles) issue_stage(kt + 1, (kt + 1) & 1);
        else CP_COMMIT();
        CP_WAIT1();
        __syncthreads();

        uint32_t stb = smb + (kt & 1) * STAGE_B;
        #pragma unroll
        for (int kk = 0; kk < 2; kk++) {
            uint32_t ah[4][4], al[4][4], bh[4][2], bl[4][2];
            #pragma unroll
            for (int mi = 0; mi < 4; mi++) {
                uint32_t aoff = stb + (aRowSel + (uint32_t)mi * 16 * RS + kk * 16) * 2;
                ldsm_x4(ah[mi], aoff);
                ldsm_x4(al[mi], aoff + TILE_B);
            }
            #pragma unroll
            for (int nj = 0; nj < 2; nj++) {
                uint32_t boff = stb + 2 * TILE_B + (bRowSel4 + (uint32_t)nj * 16 * RS + kk * 16) * 2;
                ldsm_x4(&bh[nj * 2][0], boff);
                ldsm_x4(&bl[nj * 2][0], boff + TILE_B);
            }
            #pragma unroll
            for (int mi = 0; mi < 4; mi++)
                #pragma unroll
                for (int ni = 0; ni < 4; ni++) {
                    mma16816(acc[mi][ni], ah[mi], bh[ni]);
                    mma16816(acc[mi][ni], ah[mi], bl[ni]);
                    mma16816(acc[mi][ni], al[mi], bh[ni]);
                }
        }
        __syncthreads();
    }

    // ---- epilogue ----
    int r0 = lane >> 2, c0 = (lane & 3) << 1;
    const float* bp = bias ? bias + (size_t)e * sBias : nullptr;
    #pragma unroll
    for (int mi = 0; mi < 4; mi++) {
        #pragma unroll
        for (int q2 = 0; q2 < 2; q2++) {
            int m = m0 + wm * 64 + mi * 16 + r0 + q2 * 8;
            if (m >= M) continue;
            size_t rowoff = (size_t)e * sC + (size_t)m * ldc;
            size_t resoff = (size_t)m * ldc;
            #pragma unroll
            for (int ni = 0; ni < 4; ni++) {
                int n = n0 + wn * 32 + ni * 8 + c0;
                if (n >= Nreal) continue;
                float v0 = acc[mi][ni][q2 * 2 + 0];
                float v1 = acc[mi][ni][q2 * 2 + 1];
                if (bp)    { v0 += bp[n];  v1 += bp[n + 1]; }
                if (resid) { v0 += resid[resoff + n]; v1 += resid[resoff + n + 1]; }
                if (act == 1)      { v0 = v0 / (1.f + __expf(-v0)); v1 = v1 / (1.f + __expf(-v1)); }
                else if (act == 2) { v0 = (v0 > 20.f) ? v0 : log1pf(__expf(v0));
                                     v1 = (v1 > 20.f) ? v1 : log1pf(__expf(v1)); }
                if (kSplit > 1) {
                    atomicAdd(&C[rowoff + n], v0);
                    atomicAdd(&C[rowoff + n + 1], v1);
                } else {
                    if (C) { float2 f2 = {v0, v1}; *(float2*)&C[rowoff + n] = f2; }
                    if (Chi) {
                        __nv_bfloat16 h0, h1, l0, l1;
                        split2bf(v0, h0, l0); split2bf(v1, h1, l1);
                        __nv_bfloat162 ph = {h0, h1}, pl = {l0, l1};
                        *(__nv_bfloat162*)&Chi[rowoff + n] = ph;
                        *(__nv_bfloat162*)&Clo[rowoff + n] = pl;
                    }
                }
            }
        }
    }
}

// ---------------- LayerNorm (fused bf16 hi/lo; optional fused router) --------
__global__ __launch_bounds__(256) void ln_kernel(
    const float* __restrict__ x,
    __nv_bfloat16* __restrict__ outH, __nv_bfloat16* __restrict__ outL,
    const float* __restrict__ g, const float* __restrict__ b,
    const float* __restrict__ rw,          // router weights [8, DD] or null
    float* __restrict__ probs_out)         // [TOK, 8] or null
{
    int tok = blockIdx.x;
    int i = threadIdx.x << 2;
    const float* xr = x + (size_t)tok * DD;
    float4 v = *(const float4*)&xr[i];
    float s  = v.x + v.y + v.z + v.w;
    float s2 = v.x*v.x + v.y*v.y + v.z*v.z + v.w*v.w;
    #pragma unroll
    for (int o = 16; o > 0; o >>= 1) {
        s  += __shfl_xor_sync(0xffffffffu, s,  o);
        s2 += __shfl_xor_sync(0xffffffffu, s2, o);
    }
    __shared__ float sh[16];
    __shared__ float shl[8][8];
    int w = threadIdx.x >> 5;
    int lane = threadIdx.x & 31;
    if (lane == 0) { sh[w] = s; sh[8 + w] = s2; }
    __syncthreads();
    s = 0.f; s2 = 0.f;
    #pragma unroll
    for (int k = 0; k < 8; k++) { s += sh[k]; s2 += sh[8 + k]; }
    float mu  = s * (1.0f / DD);
    float var = s2 * (1.0f / DD) - mu * mu;
    float rr = rsqrtf(var + 1e-5f);
    float4 gv = *(const float4*)&g[i];
    float4 bv = *(const float4*)&b[i];
    float4 o4;
    o4.x = (v.x - mu) * rr * gv.x + bv.x;
    o4.y = (v.y - mu) * rr * gv.y + bv.y;
    o4.z = (v.z - mu) * rr * gv.z + bv.z;
    o4.w = (v.w - mu) * rr * gv.w + bv.w;
    size_t off = (size_t)tok * DD + i;
    __nv_bfloat16 h0,h1,h2,h3,l0,l1,l2,l3;
    split2bf(o4.x,h0,l0); split2bf(o4.y,h1,l1); split2bf(o4.z,h2,l2); split2bf(o4.w,h3,l3);
    __nv_bfloat162 ph0={h0,h1}, ph1={h2,h3}, pl0={l0,l1}, pl1={l2,l3};
    uint2 uh = { *(uint32_t*)&ph0, *(uint32_t*)&ph1 };
    uint2 ul = { *(uint32_t*)&pl0, *(uint32_t*)&pl1 };
    *(uint2*)&outH[off] = uh;
    *(uint2*)&outL[off] = ul;

    // ---- fused router (MoE LN only) ----
    if (rw) {
        float lg[8];
        #pragma unroll
        for (int e = 0; e < 8; e++) {
            float4 wv = *(const float4*)&rw[e * DD + i];
            lg[e] = o4.x*wv.x + o4.y*wv.y + o4.z*wv.z + o4.w*wv.w;
        }
        #pragma unroll
        for (int e = 0; e < 8; e++)
            #pragma unroll
            for (int o = 16; o > 0; o >>= 1)
                lg[e] += __shfl_xor_sync(0xffffffffu, lg[e], o);
        if (lane == 0) {
            #pragma unroll
            for (int e = 0; e < 8; e++) shl[w][e] = lg[e];
        }
        __syncthreads();
        if (threadIdx.x == 0) {
            float p[8];
            #pragma unroll
            for (int e = 0; e < 8; e++) {
                float t = 0.f;
                #pragma unroll
                for (int k = 0; k < 8; k++) t += shl[k][e];
                p[e] = t;
            }
            float mx = p[0];
            #pragma unroll
            for (int e = 1; e < 8; e++) mx = fmaxf(mx, p[e]);
            float ssum = 0.f;
            #pragma unroll
            for (int e = 0; e < 8; e++) { p[e] = __expf(p[e] - mx); ssum += p[e]; }
            float inv = 1.f / ssum;
            #pragma unroll
            for (int e = 0; e < 8; e++) { p[e] *= inv; probs_out[(size_t)tok * 8 + e] = p[e]; }
            int i0 = 0; float v0 = p[0];
            #pragma unroll
            for (int e = 1; e < 8; e++) if (p[e] > v0) { v0 = p[e]; i0 = e; }
            int i1 = -1; float v1 = -1.f;
            #pragma unroll
            for (int e = 0; e < 8; e++) if (e != i0 && p[e] > v1) { v1 = p[e]; i1 = e; }
            float wn = 1.f / (v0 + v1);
            int p0 = atomicAdd(&g_cnt[i0], 1);
            int p1 = atomicAdd(&g_cnt[i1], 1);
            g_list[i0 * CAP + p0] = tok;
            g_list[i1 * CAP + p1] = tok;
            g_slot[tok * 2 + 0] = i0 * CAP + p0;
            g_slot[tok * 2 + 1] = i1 * CAP + p1;
            g_wgt[tok * 2 + 0] = v0 * wn;
            g_wgt[tok * 2 + 1] = v1 * wn;
        }
    }
}

// ---------------- causal depthwise conv (KC=4) + SiLU + proj zero-fill -------
__global__ __launch_bounds__(256) void conv_silu_kernel(
    const float* __restrict__ xz,
    const float* __restrict__ cw,
    const float* __restrict__ cb,
    float* __restrict__ xc,
    __nv_bfloat16* __restrict__ xch,
    __nv_bfloat16* __restrict__ xcl,
    float* __restrict__ projZero)
{
    int idx = blockIdx.x * 256 + threadIdx.x;
    if (idx < (TOK * PROJN) / 4)
        *(float4*)&projZero[(size_t)idx << 2] = make_float4(0.f, 0.f, 0.f, 0.f);
    int d = (idx & 511) << 2;
    int m = idx >> 9;
    int t = m & (TT - 1);
    const float* base = xz + (size_t)m * XZN + d;
    float4 z4 = make_float4(0.f,0.f,0.f,0.f);
    float4 x3 = (t >= 3) ? *(const float4*)(base - 3 * XZN) : z4;
    float4 x2 = (t >= 2) ? *(const float4*)(base - 2 * XZN) : z4;
    float4 x1 = (t >= 1) ? *(const float4*)(base - XZN) : z4;
    float4 x0 = *(const float4*)base;
    float4 cbv = *(const float4*)&cb[d];
    float4 w0 = *(const float4*)&cw[(d + 0) * 4];
    float4 w1 = *(const float4*)&cw[(d + 1) * 4];
    float4 w2 = *(const float4*)&cw[(d + 2) * 4];
    float4 w3 = *(const float4*)&cw[(d + 3) * 4];
    float4 a;
    a.x = cbv.x + w0.x*x3.x + w0.y*x2.x + w0.z*x1.x + w0.w*x0.x;
    a.y = cbv.y + w1.x*x3.y + w1.y*x2.y + w1.z*x1.y + w1.w*x0.y;
    a.z = cbv.z + w2.x*x3.z + w2.y*x2.z + w2.z*x1.z + w2.w*x0.z;
    a.w = cbv.w + w3.x*x3.w + w3.y*x2.w + w3.z*x1.w + w3.w*x0.w;
    a.x = a.x / (1.f + __expf(-a.x));
    a.y = a.y / (1.f + __expf(-a.y));
    a.z = a.z / (1.f + __expf(-a.z));
    a.w = a.w / (1.f + __expf(-a.w));
    size_t off = (size_t)m * DI + d;
    *(float4*)&xc[off] = a;
    __nv_bfloat16 h0,h1,h2,h3,l0,l1,l2,l3;
    split2bf(a.x,h0,l0); split2bf(a.y,h1,l1); split2bf(a.z,h2,l2); split2bf(a.w,h3,l3);
    __nv_bfloat162 ph0={h0,h1}, ph1={h2,h3}, pl0={l0,l1}, pl1={l2,l3};
    uint2 uh = { *(uint32_t*)&ph0, *(uint32_t*)&ph1 };
    uint2 ul = { *(uint32_t*)&pl0, *(uint32_t*)&pl1 };
    *(uint2*)&xch[off] = uh;
    *(uint2*)&xcl[off] = ul;
}

// ---------------- blocked selective scan ----------------
__global__ __launch_bounds__(256) void scan1_kernel(
    const float* __restrict__ proj,
    const float* __restrict__ xc,
    const float* __restrict__ dt,
    const float* __restrict__ A_log,
    float* __restrict__ hend,
    float* __restrict__ sumdt)
{
    // zero g_cnt early (well before fused router in ln2)
    if (blockIdx.x == 0 && blockIdx.y == 0 && blockIdx.z == 0 && threadIdx.x < NE)
        g_cnt[threadIdx.x] = 0;

    int b = blockIdx.z, chunk = blockIdx.y;
    int lane = threadIdx.x & 31;
    int ch = lane >> 2, ng = lane & 3;
    int d = (blockIdx.x * 8 + (threadIdx.x >> 5)) * 8 + ch;

    float4 Al = *(const float4*)&A_log[(size_t)d * NSTATE + ng * 4];
    float a0 = -__expf(Al.x), a1 = -__expf(Al.y), a2 = -__expf(Al.z), a3 = -__expf(Al.w);
    float h0 = 0.f, h1 = 0.f, h2 = 0.f, h3 = 0.f, sdt = 0.f;
    size_t tokbase = (size_t)b * TT + (size_t)chunk * CL;

    for (int t = 0; t < CL; t++) {
        size_t tok = tokbase + t;
        float4 Bv = *(const float4*)&proj[tok * PROJN + DTR + ng * 4];
        float xt  = xc[tok * DI + d];
        float dtt = dt[tok * DI + d];
        sdt += dtt;
        float dx = dtt * xt;
        h0 = __expf(dtt * a0) * h0 + dx * Bv.x;
        h1 = __expf(dtt * a1) * h1 + dx * Bv.y;
        h2 = __expf(dtt * a2) * h2 + dx * Bv.z;
        h3 = __expf(dtt * a3) * h3 + dx * Bv.w;
    }
    size_t cdi = ((size_t)(b * NCHUNK + chunk) * DI + d);
    float4 hv = {h0, h1, h2, h3};
    *(float4*)&hend[cdi * NSTATE + ng * 4] = hv;
    if (ng == 0) sumdt[cdi] = sdt;
}

__global__ __launch_bounds__(256) void scomb_kernel(
    const float* __restrict__ A_log,
    const float* __restrict__ hend,
    const float* __restrict__ sumdt,
    float* __restrict__ hin)
{
    int idx = blockIdx.x * 256 + threadIdx.x;
    int n = idx & (NSTATE - 1);
    int d = (idx >> 4) & (DI - 1);
    int b = idx >> 15;
    float a = -__expf(A_log[(size_t)d * NSTATE + n]);
    float h = 0.f;
    #pragma unroll
    for (int c = 0; c < NCHUNK; c++) {
        size_t cdi = (size_t)(b * NCHUNK + c) * DI + d;
        hin[cdi * NSTATE + n] = h;
        h = __expf(a * sumdt[cdi]) * h + hend[cdi * NSTATE + n];
    }
}

__global__ __launch_bounds__(256) void scan2_kernel(
    const float* __restrict__ proj,
    const float* __restrict__ xc,
    const float* __restrict__ dt,
    const float* __restrict__ xz,
    const float* __restrict__ A_log,
    const float* __restrict__ D_skip,
    const float* __restrict__ hin,
    __nv_bfloat16* __restrict__ ybh,
    __nv_bfloat16* __restrict__ ybl)
{
    int b = blockIdx.z, chunk = blockIdx.y;
    int lane = threadIdx.x & 31;
    int ch = lane >> 2, ng = lane & 3;
    int d = (blockIdx.x * 8 + (threadIdx.x >> 5)) * 8 + ch;

    float4 Al = *(const float4*)&A_log[(size_t)d * NSTATE + ng * 4];
    float a0 = -__expf(Al.x), a1 = -__expf(Al.y), a2 = -__expf(Al.z), a3 = -__expf(Al.w);
    size_t cdi = (size_t)(b * NCHUNK + chunk) * DI + d;
    float4 hv = *(const float4*)&hin[cdi * NSTATE + ng * 4];
    float h0 = hv.x, h1 = hv.y, h2 = hv.z, h3 = hv.w;
    float dsk = D_skip[d];
    size_t tokbase = (size_t)b * TT + (size_t)chunk * CL;

    for (int t = 0; t < CL; t++) {
        size_t tok = tokbase + t;
        float4 Bv = *(const float4*)&proj[tok * PROJN + DTR + ng * 4];
        float4 Cv = *(const float4*)&proj[tok * PROJN + DTR + NSTATE + ng * 4];
        float xt  = xc[tok * DI + d];
        float dtt = dt[tok * DI + d];
        float dx = dtt * xt;
        h0 = __expf(dtt * a0) * h0 + dx * Bv.x;
        h1 = __expf(dtt * a1) * h1 + dx * Bv.y;
        h2 = __expf(dtt * a2) * h2 + dx * Bv.z;
        h3 = __expf(dtt * a3) * h3 + dx * Bv.w;
        float y = h0 * Cv.x + h1 * Cv.y + h2 * Cv.z + h3 * Cv.w;
        y += __shfl_xor_sync(0xffffffffu, y, 1);
        y += __shfl_xor_sync(0xffffffffu, y, 2);
        if (ng == 0) {
            float z = xz[tok * XZN + DI + d];
            float sil = z / (1.f + __expf(-z));
            float v = (y + xt * dsk) * sil;
            __nv_bfloat16 hh, ll;
            split2bf(v, hh, ll);
            ybh[tok * DI + d] = hh;
            ybl[tok * DI + d] = ll;
        }
    }
}

// ---------------- combine ----------------
__global__ __launch_bounds__(256) void combine_kernel(float* __restrict__ hout,
                                                      const float* __restrict__ ye)
{
    int tok = blockIdx.x;
    int j = threadIdx.x << 2;
    int s0 = g_slot[tok * 2], s1 = g_slot[tok * 2 + 1];
    float w0 = g_wgt[tok * 2], w1 = g_wgt[tok * 2 + 1];
    float4 a  = *(float4*)&hout[(size_t)tok * DD + j];
    float4 y0 = *(const float4*)&ye[(size_t)s0 * DD + j];
    float4 y1 = *(const float4*)&ye[(size_t)s1 * DD + j];
    a.x += w0 * y0.x + w1 * y1.x;
    a.y += w0 * y0.y + w1 * y1.y;
    a.z += w0 * y0.z + w1 * y1.z;
    a.w += w0 * y0.w + w1 * y1.w;
    *(float4*)&hout[(size_t)tok * DD + j] = a;
}

// ---------------- launcher ----------------
static inline int vblk(long long totalVec) { return (int)((totalVec + 255) / 256); }

extern "C" void kernel_launch(void* const* d_in, const int* in_sizes, int n_in,
                              void* d_out, int out_size)
{
    const float* x        = (const float*)d_in[0];
    const float* lnm_g    = (const float*)d_in[1];
    const float* lnm_b    = (const float*)d_in[2];
    const float* lne_g    = (const float*)d_in[3];
    const float* lne_b    = (const float*)d_in[4];
    const float* in_w     = (const float*)d_in[5];
    const float* in_b     = (const float*)d_in[6];
    const float* conv_w   = (const float*)d_in[7];
    const float* conv_b   = (const float*)d_in[8];
    const float* xproj_w  = (const float*)d_in[9];
    const float* dt_w     = (const float*)d_in[10];
    const float* dt_b     = (const float*)d_in[11];
    const float* A_log    = (const float*)d_in[12];
    const float* D_skip   = (const float*)d_in[13];
    const float* out_w    = (const float*)d_in[14];
    const float* router_w = (const float*)d_in[15];
    const float* w1       = (const float*)d_in[16];
    const float* b1       = (const float*)d_in[17];
    const float* w2       = (const float*)d_in[18];
    const float* b2       = (const float*)d_in[19];

    float* out_h     = (float*)d_out;
    float* out_probs = out_h + (size_t)TOK * DD;

    unsigned char* S;
    cudaGetSymbolAddress((void**)&S, g_scratch);
    float* xz    = (float*)(S + O_XZ);
    float* xc    = (float*)(S + O_XC);
    float* proj  = (float*)(S + O_PROJ);
    float* dtb   = (float*)(S + O_DT);
    float* ye    = (float*)(S + O_YE);
    float* hend  = (float*)(S + O_HEND);
    float* hin   = (float*)(S + O_HIN);
    float* sdt   = (float*)(S + O_SDT);
    __nv_bfloat16* hnh  = (__nv_bfloat16*)(S + O_HNH);
    __nv_bfloat16* hnl  = (__nv_bfloat16*)(S + O_HNL);
    __nv_bfloat16* inwh = (__nv_bfloat16*)(S + O_INWH);
    __nv_bfloat16* inwl = (__nv_bfloat16*)(S + O_INWL);
    __nv_bfloat16* xch  = (__nv_bfloat16*)(S + O_XCH);
    __nv_bfloat16* xcl  = (__nv_bfloat16*)(S + O_XCL);
    __nv_bfloat16* xpwh = (__nv_bfloat16*)(S + O_XPWH);
    __nv_bfloat16* xpwl = (__nv_bfloat16*)(S + O_XPWL);
    __nv_bfloat16* dtah = (__nv_bfloat16*)(S + O_DTAH);
    __nv_bfloat16* dtal = (__nv_bfloat16*)(S + O_DTAL);
    __nv_bfloat16* dtwh = (__nv_bfloat16*)(S + O_DTWH);
    __nv_bfloat16* dtwl = (__nv_bfloat16*)(S + O_DTWL);
    __nv_bfloat16* ybh  = (__nv_bfloat16*)(S + O_YBH);
    __nv_bfloat16* ybl  = (__nv_bfloat16*)(S + O_YBL);
    __nv_bfloat16* owh  = (__nv_bfloat16*)(S + O_OWH);
    __nv_bfloat16* owl  = (__nv_bfloat16*)(S + O_OWL);
    __nv_bfloat16* hmh  = (__nv_bfloat16*)(S + O_HMH);
    __nv_bfloat16* hml  = (__nv_bfloat16*)(S + O_HML);
    __nv_bfloat16* w1h  = (__nv_bfloat16*)(S + O_W1H);
    __nv_bfloat16* w1l  = (__nv_bfloat16*)(S + O_W1L);
    __nv_bfloat16* w2h  = (__nv_bfloat16*)(S + O_W2H);
    __nv_bfloat16* w2l  = (__nv_bfloat16*)(S + O_W2L);
    __nv_bfloat16* h1h  = (__nv_bfloat16*)(S + O_H1H);
    __nv_bfloat16* h1l  = (__nv_bfloat16*)(S + O_H1L);

    cudaFuncSetAttribute(tgemm, cudaFuncAttributeMaxDynamicSharedMemorySize, TG_SMEM);

    cudaStream_t s2 = g_sc.s2;
    cudaEvent_t* ev = g_sc.ev;

    // ---- fork side stream: all weight splits (depend only on inputs) ----
    cudaEventRecord(ev[0], 0);
    cudaStreamWaitEvent(s2, ev[0], 0);
    split4_kernel<<<vblk((long long)XZN*DD/4), 256, 0, s2>>>(in_w, DD, XZN, inwh, inwl, 8, (long long)XZN*DD/4);
    cudaEventRecord(ev[1], s2);
    split4_kernel<<<vblk((long long)128*DI/4), 256, 0, s2>>>(xproj_w, DI, PROJN, xpwh, xpwl, 9, (long long)128*DI/4);
    split4_kernel<<<vblk((long long)DI*DTR/4), 256, 0, s2>>>(dt_w, DTR, DI, dtwh, dtwl, 4, (long long)DI*DTR/4);
    cudaEventRecord(ev[2], s2);
    split4_kernel<<<vblk((long long)DD*DI/4), 256, 0, s2>>>(out_w, DI, DD, owh, owl, 9, (long long)DD*DI/4);
    cudaEventRecord(ev[3], s2);
    split4_kernel<<<vblk((long long)NE*DFF*DD/4), 256, 0, s2>>>(w1, DD, NE*DFF, w1h, w1l, 8, (long long)NE*DFF*DD/4);
    split4_kernel<<<vblk((long long)NE*DD*DFF/4), 256, 0, s2>>>(w2, DFF, NE*DD, w2h, w2l, 9, (long long)NE*DD*DFF/4);
    cudaEventRecord(ev[4], s2);

    // ---- main chain ----
    // 1. LN (mamba) -> hi/lo only (no router)
    ln_kernel<<<TOK, 256>>>(x, hnh, hnl, lnm_g, lnm_b, nullptr, nullptr);
    // 2. in_proj (needs in_w split)
    cudaStreamWaitEvent(0, ev[1], 0);
    tgemm<<<dim3(XZN/128, TOK/128, 1), 256, TG_SMEM>>>(
        hnh, hnl, DD, 0, inwh, inwl, DD, 0,
        xz, XZN, 0, nullptr, nullptr,
        TOK, XZN, DD, in_b, 0, nullptr, 0, 0, 0, 1);
    // 3. conv + silu (+ zero proj)
    conv_silu_kernel<<<(TOK*DI/4)/256, 256>>>(xz, conv_w, conv_b, xc, xch, xcl, proj);
    // 4. x_proj split-K=8 (needs xpw split)
    cudaStreamWaitEvent(0, ev[2], 0);
    tgemm<<<dim3(1, TOK/128, 8), 256, TG_SMEM>>>(
        xch, xcl, DI, 0, xpwh, xpwl, DI, 0,
        proj, PROJN, 0, nullptr, nullptr,
        TOK, PROJN, DI, nullptr, 0, nullptr, 0, 0, 0, 8);
    // 5. dt_r split (needs proj)
    split4_kernel<<<vblk((long long)TOK*DTR/4), 256>>>(proj, PROJN, TOK, dtah, dtal, 4, (long long)TOK*DTR/4);
    // 6. dt_proj
    tgemm<<<dim3(DI/128, TOK/128, 1), 256, TG_SMEM>>>(
        dtah, dtal, DTR, 0, dtwh, dtwl, DTR, 0,
        dtb, DI, 0, nullptr, nullptr,
        TOK, DI, DTR, dt_b, 0, nullptr, 2, 0, 0, 1);
    // 7. blocked selective scan (NCHUNK=64); scan1 also zeroes g_cnt
    scan1_kernel<<<dim3(32, NCHUNK, BATCH), 256>>>(proj, xc, dtb, A_log, hend, sdt);
    scomb_kernel<<<(BATCH*DI*NSTATE)/256, 256>>>(A_log, hend, sdt, hin);
    scan2_kernel<<<dim3(32, NCHUNK, BATCH), 256>>>(proj, xc, dtb, xz, A_log, D_skip, hin, ybh, ybl);
    // 8. out_proj + residual (needs out_w split)
    cudaStreamWaitEvent(0, ev[3], 0);
    tgemm<<<dim3(DD/128, TOK/128, 1), 256, TG_SMEM>>>(
        ybh, ybl, DI, 0, owh, owl, DI, 0,
        out_h, DD, 0, nullptr, nullptr,
        TOK, DD, DI, nullptr, 0, x, 0, 0, 0, 1);
    // 9. LN (moe) + fused router/top2/lists
    ln_kernel<<<TOK, 256>>>(out_h, hmh, hml, lne_g, lne_b, router_w, out_probs);
    // 10. expert GEMM 1 (needs w1/w2 splits)
    cudaStreamWaitEvent(0, ev[4], 0);
    tgemm<<<dim3(DFF/128, CAP/128, NE), 256, TG_SMEM>>>(
        hmh, hml, DD, 0, w1h, w1l, DD, (unsigned long long)DFF*DD,
        nullptr, DFF, (unsigned long long)CAP*DFF, h1h, h1l,
        0, DFF, DD, b1, DFF, nullptr, 1, 1, 1, 1);
    // 11. expert GEMM 2
    tgemm<<<dim3(DD/128, CAP/128, NE), 256, TG_SMEM>>>(
        h1h, h1l, DFF, (unsigned long long)CAP*DFF, w2h, w2l, DFF, (unsigned long long)DD*DFF,
        ye, DD, (unsigned long long)CAP*DD, nullptr, nullptr,
        0, DD, DFF, b2, DD, nullptr, 0, 0, 1, 1);
    // 12. combine
    combine_kernel<<<TOK, 256>>>(out_h, ye);
}